// round 7
// baseline (speedup 1.0000x reference)
#include <cuda_runtime.h>
#include <stdint.h>

#define BATCH 128
#define NANCH 16800
#define NQ (NANCH / 4)            // 4200 uint4/float4 per row
#define NEG_RATIO 3
#define SCALE_XY 10.0f
#define SCALE_WH 5.0f
#define T 1024
#define NW (T / 32)               // 32 warps
#define NIT ((NQ + T - 1) / T)    // 5
#define NBINS 34816u              // bits >> 15 for values < 512
#define FLT_EPS_ 1.1920929e-07f

// Cross-block scratch (allocation-free rule: __device__ globals)
__device__ float g_row_lossb[BATCH];
__device__ float g_row_lossl[BATCH];
__device__ int   g_row_posn[BATCH];
__device__ int   g_done = 0;

extern __shared__ unsigned s_bits[];  // [NANCH] labels_neg bit patterns

__device__ __forceinline__ float warp_sum(float v) {
    #pragma unroll
    for (int o = 16; o > 0; o >>= 1) v += __shfl_down_sync(0xFFFFFFFFu, v, o);
    return v;
}
__device__ __forceinline__ int warp_sum_i(int v) {
    #pragma unroll
    for (int o = 16; o > 0; o >>= 1) v += __shfl_down_sync(0xFFFFFFFFu, v, o);
    return v;
}

__global__ __launch_bounds__(T, 1)
void od_fused(const float* __restrict__ pbboxs,
              const float* __restrict__ plabels,
              const float* __restrict__ gbboxs,
              const float* __restrict__ glabels,
              const float* __restrict__ ancs,
              float* __restrict__ out, int out_size) {
    const int b    = blockIdx.x;
    const int tid  = threadIdx.x;
    const int lane = tid & 31;
    const int wid  = tid >> 5;

    __shared__ float    s_wf1[NW], s_wf2[NW];
    __shared__ int      s_wi1[NW], s_wi2[NW];
    __shared__ float    s_sl1, s_bce, s_top;
    __shared__ int      s_cnt, s_last;
    __shared__ unsigned s_lo, s_hi;
    __shared__ float    s_red[NW * 3];

    const float4* pl4 = (const float4*)(plabels + (size_t)b * NANCH);
    const float4* gl4 = (const float4*)(glabels + (size_t)b * NANCH);
    const float4* pb  = (const float4*)pbboxs + (size_t)b * NANCH;
    const float4* gb  = (const float4*)gbboxs + (size_t)b * NANCH;
    const float4* an  = (const float4*)ancs;

    // ---- Main pass: BCE + positive SmoothL1; bits -> smem (no atomics) ----
    float acc_sl1 = 0.f, acc_bce = 0.f;
    int cnt = 0;
    #pragma unroll
    for (int it = 0; it < NIT; it++) {
        const int i4 = tid + it * T;
        if (i4 < NQ) {
            float4 xv = pl4[i4];
            float4 yv = gl4[i4];
            uint4 w;
            #pragma unroll
            for (int c = 0; c < 4; c++) {
                float x = (c == 0) ? xv.x : (c == 1) ? xv.y : (c == 2) ? xv.z : xv.w;
                float y = (c == 0) ? yv.x : (c == 1) ? yv.y : (c == 2) ? yv.z : yv.w;
                float bce = fmaxf(x, 0.f) - x * y + __logf(1.f + __expf(-fabsf(x)));
                unsigned bits;
                if (y > 0.f) {
                    const int i = 4 * i4 + c;
                    float4 p = pb[i];
                    float4 g = gb[i];
                    float4 a = an[i];
                    float inv_az = 1.f / a.z;
                    float inv_aw = 1.f / a.w;
                    float d0 = p.x - SCALE_XY * (g.x - a.x) * inv_az;
                    float d1 = p.y - SCALE_XY * (g.y - a.y) * inv_aw;
                    float d2 = p.z - SCALE_WH * __logf(g.z * inv_az);
                    float d3 = p.w - SCALE_WH * __logf(g.w * inv_aw);
                    float sl1 = 0.f, ad;
                    ad = fabsf(d0); sl1 += (ad < 1.f) ? 0.5f * d0 * d0 : ad - 0.5f;
                    ad = fabsf(d1); sl1 += (ad < 1.f) ? 0.5f * d1 * d1 : ad - 0.5f;
                    ad = fabsf(d2); sl1 += (ad < 1.f) ? 0.5f * d2 * d2 : ad - 0.5f;
                    ad = fabsf(d3); sl1 += (ad < 1.f) ? 0.5f * d3 * d3 : ad - 0.5f;
                    acc_sl1 += sl1;
                    acc_bce += bce;
                    cnt++;
                    bits = 0u;   // excluded from mining
                } else {
                    bits = __float_as_uint(bce);  // bce >= 0: bit order == value order
                }
                if (c == 0) w.x = bits; else if (c == 1) w.y = bits;
                else if (c == 2) w.z = bits; else w.w = bits;
            }
            ((uint4*)s_bits)[i4] = w;
        }
    }
    // row scalar reduction: per-warp partials -> warp0 combine (no atomics)
    {
        float w1 = warp_sum(acc_sl1);
        float w2 = warp_sum(acc_bce);
        int   w3 = warp_sum_i(cnt);
        if (lane == 0) { s_wf1[wid] = w1; s_wf2[wid] = w2; s_wi1[wid] = w3; }
    }
    __syncthreads();
    if (tid < 32) {
        float v1 = warp_sum(s_wf1[lane]);
        float v2 = warp_sum(s_wf2[lane]);
        int   v3 = warp_sum_i(s_wi1[lane]);
        if (lane == 0) {
            s_sl1 = v1; s_bce = v2; s_cnt = v3;
            s_lo = 0u; s_hi = NBINS; s_top = 0.f;
        }
    }
    __syncthreads();

    const int pos_num = s_cnt;
    int K = NEG_RATIO * pos_num;
    if (K > NANCH) K = NANCH;

    if (K > 0) {
        // ---- 4-way binary search on the bin threshold (pure ALU counting) ----
        #pragma unroll 1
        for (int s = 0; s < 10; s++) {
            const unsigned lo = s_lo, hi = s_hi;
            const unsigned w = hi - lo;
            if (w <= 1u) break;   // uniform: all threads read same shared state
            unsigned q1 = w >> 2, q2 = w >> 1, q3 = (3u * w) >> 2;
            const unsigned b1 = lo + (q1 > 1u ? q1 : 1u);
            const unsigned b2 = lo + (q2 > 2u ? q2 : 2u);
            const unsigned b3 = lo + (q3 > 3u ? q3 : 3u);
            const unsigned B1 = b1 << 15, B2 = b2 << 15, B3 = b3 << 15;

            int c1 = 0, c2 = 0, c3 = 0;
            #pragma unroll
            for (int it = 0; it < NIT; it++) {
                const int i4 = tid + it * T;
                if (i4 < NQ) {
                    uint4 u = ((const uint4*)s_bits)[i4];
                    c1 += (u.x >= B1) + (u.y >= B1) + (u.z >= B1) + (u.w >= B1);
                    c2 += (u.x >= B2) + (u.y >= B2) + (u.z >= B2) + (u.w >= B2);
                    c3 += (u.x >= B3) + (u.y >= B3) + (u.z >= B3) + (u.w >= B3);
                }
            }
            int p12 = c1 | (c2 << 16);           // per-thread counts <= 20, warp sums <= 640
            p12 = warp_sum_i(p12);
            c3  = warp_sum_i(c3);
            if (lane == 0) { s_wi1[wid] = p12; s_wi2[wid] = c3; }
            __syncthreads();
            if (tid < 32) {
                int v12 = warp_sum_i(s_wi1[lane]);
                int v3  = warp_sum_i(s_wi2[lane]);
                if (lane == 0) {
                    const int C1 = v12 & 0xFFFF;
                    const int C2 = v12 >> 16;
                    const int C3 = v3;
                    if (C3 >= K)      { s_lo = b3; }
                    else if (C2 >= K) { s_lo = b2; s_hi = b3; }
                    else if (C1 >= K) { s_lo = b1; s_hi = b2; }
                    else              { s_hi = b1; }
                }
            }
            __syncthreads();
        }

        // ---- Final sweep: exact sum above tie bin + tie count/sum ----
        const unsigned tb  = s_lo;
        const unsigned Bhi = (tb + 1u) << 15;
        const unsigned Blo = tb << 15;
        float sa = 0.f, ts = 0.f;
        int ca = 0, tc = 0;
        #pragma unroll
        for (int it = 0; it < NIT; it++) {
            const int i4 = tid + it * T;
            if (i4 < NQ) {
                uint4 u = ((const uint4*)s_bits)[i4];
                #pragma unroll
                for (int c = 0; c < 4; c++) {
                    unsigned uc = (c == 0) ? u.x : (c == 1) ? u.y : (c == 2) ? u.z : u.w;
                    if (uc >= Bhi)      { sa += __uint_as_float(uc); ca++; }
                    else if (uc >= Blo) { ts += __uint_as_float(uc); tc++; }
                }
            }
        }
        sa = warp_sum(sa);
        ts = warp_sum(ts);
        int pct = warp_sum_i(ca | (tc << 16));
        if (lane == 0) { s_wf1[wid] = sa; s_wf2[wid] = ts; s_wi1[wid] = pct; }
        __syncthreads();
        if (tid < 32) {
            float v1 = warp_sum(s_wf1[lane]);
            float v2 = warp_sum(s_wf2[lane]);
            int   vc = warp_sum_i(s_wi1[lane]);
            if (lane == 0) {
                const int CA = vc & 0xFFFF;
                const int TC = vc >> 16;
                const int kr = K - CA;
                const float avg = v2 / (float)(TC > 0 ? TC : 1);
                s_top = v1 + (float)kr * avg;
            }
        }
        __syncthreads();
    }
    const float sum_top = s_top;

    // ---- Publish row; last block does the final reduction ----
    if (tid == 0) {
        g_row_posn[b]  = pos_num;
        g_row_lossb[b] = s_sl1;
        g_row_lossl[b] = s_bce + sum_top;
        __threadfence();
        int prev = atomicAdd(&g_done, 1);
        s_last = (prev == BATCH - 1);
    }
    __syncthreads();

    if (s_last) {
        float vlb = 0.f, vll = 0.f, vm = 0.f;
        if (tid < BATCH) {
            float pn  = (float)((volatile int*)g_row_posn)[tid];
            float lbv = ((volatile float*)g_row_lossb)[tid];
            float llv = ((volatile float*)g_row_lossl)[tid];
            float mask = (pn > 0.f) ? 1.f : 0.f;
            float wgt  = mask / fmaxf(pn, FLT_EPS_);
            vlb = lbv * wgt;
            vll = llv * wgt;
            vm  = wgt;
        }
        vlb = warp_sum(vlb);
        vll = warp_sum(vll);
        vm  = warp_sum(vm);
        if (lane == 0) {
            s_red[wid * 3 + 0] = vlb;
            s_red[wid * 3 + 1] = vll;
            s_red[wid * 3 + 2] = vm;
        }
        __syncthreads();
        if (tid == 0) {
            float slb = 0.f, sll = 0.f, sm = 0.f;
            #pragma unroll
            for (int w = 0; w < NW; w++) {
                slb += s_red[w * 3 + 0];
                sll += s_red[w * 3 + 1];
                sm  += s_red[w * 3 + 2];
            }
            const float lb = slb / (float)BATCH;
            const float ll = sll / (float)BATCH;
            const float total = (lb + ll) * (sm / (float)BATCH);
            if (out_size >= 1) out[0] = total;
            if (out_size >= 2) out[1] = lb;
            if (out_size >= 3) out[2] = ll;
            g_done = 0;  // reset for next graph replay
        }
    }
}

extern "C" void kernel_launch(void* const* d_in, const int* in_sizes, int n_in,
                              void* d_out, int out_size) {
    const float* pbboxs  = (const float*)d_in[0];
    const float* plabels = (const float*)d_in[1];
    const float* gbboxs  = (const float*)d_in[2];
    const float* glabels = (const float*)d_in[3];
    const float* ancs    = (const float*)d_in[4];
    (void)in_sizes; (void)n_in;

    const size_t smem = (size_t)NANCH * sizeof(unsigned);  // 67.2 KB
    cudaFuncSetAttribute(od_fused,
                         cudaFuncAttributeMaxDynamicSharedMemorySize, (int)smem);

    od_fused<<<BATCH, T, smem>>>(pbboxs, plabels, gbboxs, glabels, ancs,
                                 (float*)d_out, out_size);
}

// round 8
// speedup vs baseline: 1.0607x; 1.0607x over previous
#include <cuda_runtime.h>
#include <stdint.h>

#define BATCH 128
#define NANCH 16800
#define NQ (NANCH / 4)            // 4200 float4 per row
#define NEG_RATIO 3
#define SCALE_XY 10.0f
#define SCALE_WH 5.0f
#define T 1024
#define NW 32
#define NIT 5                     // ceil(NQ / T)
#define CAP 4096                  // candidate buffer (expected ~2170 used)
#define P0F 1.4f                  // compaction pivot: threshold is always above this
#define FLT_EPS_ 1.1920929e-07f

// Cross-block scratch (allocation-free rule: __device__ globals)
__device__ float g_row_lossb[BATCH];
__device__ float g_row_lossl[BATCH];
__device__ int   g_row_posn[BATCH];
__device__ int   g_done = 0;

__device__ __forceinline__ float warp_sum(float v) {
    #pragma unroll
    for (int o = 16; o > 0; o >>= 1) v += __shfl_down_sync(0xFFFFFFFFu, v, o);
    return v;
}
__device__ __forceinline__ int warp_sum_i(int v) {
    #pragma unroll
    for (int o = 16; o > 0; o >>= 1) v += __shfl_down_sync(0xFFFFFFFFu, v, o);
    return v;
}
__device__ __forceinline__ unsigned warp_max_u(unsigned v) {
    #pragma unroll
    for (int o = 16; o > 0; o >>= 1) {
        unsigned u = __shfl_down_sync(0xFFFFFFFFu, v, o);
        v = (u > v) ? u : v;
    }
    return v;
}
__device__ __forceinline__ float bce_of(float x, float y) {
    return fmaxf(x, 0.f) - x * y + __logf(1.f + __expf(-fabsf(x)));
}

__global__ __launch_bounds__(T, 1)
void od_fused(const float* __restrict__ pbboxs,
              const float* __restrict__ plabels,
              const float* __restrict__ gbboxs,
              const float* __restrict__ glabels,
              const float* __restrict__ ancs,
              float* __restrict__ out, int out_size) {
    const int b    = blockIdx.x;
    const int tid  = threadIdx.x;
    const int lane = tid & 31;
    const int wid  = tid >> 5;

    __shared__ unsigned s_cand[CAP];       // 16 KB
    __shared__ float    s_wf[NW], s_wf2[NW];
    __shared__ int      s_wi[NW];
    __shared__ float    s_sl1, s_bce, s_top;
    __shared__ int      s_cnt, s_m, s_ovf, s_last;
    __shared__ unsigned s_lo, s_hi;
    __shared__ float    s_red[NW * 3];

    if (tid == 0) { s_m = 0; s_ovf = 0; s_top = 0.f; }

    const float4* pl4 = (const float4*)(plabels + (size_t)b * NANCH);
    const float4* gl4 = (const float4*)(glabels + (size_t)b * NANCH);
    const float4* pb  = (const float4*)pbboxs + (size_t)b * NANCH;
    const float4* gb  = (const float4*)gbboxs + (size_t)b * NANCH;
    const float4* an  = (const float4*)ancs;

    // ---- Prefetch streaming inputs (10 LDG.128/thread -> high MLP) ----
    float4 xa[NIT], ya[NIT];
    #pragma unroll
    for (int it = 0; it < NIT; it++) {
        const int i4 = tid + it * T;
        if (i4 < NQ) { xa[it] = pl4[i4]; ya[it] = gl4[i4]; }
        else { xa[it] = make_float4(0.f, 0.f, 0.f, 0.f); ya[it] = make_float4(0.f, 0.f, 0.f, 0.f); }
    }
    __syncthreads();  // s_m / s_ovf init visible before compaction atomics

    // ---- Main pass: BCE + positive SmoothL1 + candidate compaction ----
    float acc_sl1 = 0.f, acc_bce = 0.f;
    int cnt = 0;
    #pragma unroll
    for (int it = 0; it < NIT; it++) {
        #pragma unroll
        for (int c = 0; c < 4; c++) {
            float x = (c == 0) ? xa[it].x : (c == 1) ? xa[it].y : (c == 2) ? xa[it].z : xa[it].w;
            float y = (c == 0) ? ya[it].x : (c == 1) ? ya[it].y : (c == 2) ? ya[it].z : ya[it].w;
            float bv = bce_of(x, y);
            bool pos = (y > 0.f);    // fake tail elements have y==0 -> never pos
            if (pos) {
                const int i = ((tid + it * T) << 2) + c;
                float4 p = pb[i];
                float4 g = gb[i];
                float4 a = an[i];
                float inv_az = 1.f / a.z;
                float inv_aw = 1.f / a.w;
                float d0 = p.x - SCALE_XY * (g.x - a.x) * inv_az;
                float d1 = p.y - SCALE_XY * (g.y - a.y) * inv_aw;
                float d2 = p.z - SCALE_WH * __logf(g.z * inv_az);
                float d3 = p.w - SCALE_WH * __logf(g.w * inv_aw);
                float sl1 = 0.f, ad;
                ad = fabsf(d0); sl1 += (ad < 1.f) ? 0.5f * d0 * d0 : ad - 0.5f;
                ad = fabsf(d1); sl1 += (ad < 1.f) ? 0.5f * d1 * d1 : ad - 0.5f;
                ad = fabsf(d2); sl1 += (ad < 1.f) ? 0.5f * d2 * d2 : ad - 0.5f;
                ad = fabsf(d3); sl1 += (ad < 1.f) ? 0.5f * d3 * d3 : ad - 0.5f;
                acc_sl1 += sl1;
                acc_bce += bv;
                cnt++;
            }
            // warp-aggregated compaction of negatives with bce >= P0
            bool cand = (!pos) && (bv >= P0F);
            unsigned mk = __ballot_sync(0xFFFFFFFFu, cand);
            if (mk) {
                const int leader = __ffs(mk) - 1;
                int base = 0;
                if (lane == leader) base = atomicAdd(&s_m, __popc(mk));
                base = __shfl_sync(0xFFFFFFFFu, base, leader);
                if (cand) {
                    const int pi = base + __popc(mk & ((1u << lane) - 1u));
                    if (pi < CAP) s_cand[pi] = __float_as_uint(bv);
                    else s_ovf = 1;
                }
            }
        }
    }
    // row scalar reduction (no atomics)
    {
        float w1 = warp_sum(acc_sl1);
        float w2 = warp_sum(acc_bce);
        int   w3 = warp_sum_i(cnt);
        if (lane == 0) { s_wf[wid] = w1; s_wf2[wid] = w2; s_wi[wid] = w3; }
    }
    __syncthreads();
    if (tid < 32) {
        float v1 = warp_sum(s_wf[lane]);
        float v2 = warp_sum(s_wf2[lane]);
        int   v3 = warp_sum_i(s_wi[lane]);
        if (lane == 0) { s_sl1 = v1; s_bce = v2; s_cnt = v3; }
    }
    __syncthreads();

    const int pos_num = s_cnt;
    const int M = s_m;
    const bool ovf = (s_ovf != 0);
    int K = NEG_RATIO * pos_num;
    if (K > NANCH) K = NANCH;

    if (K > 0) {
        if (!ovf && M >= K) {
            // ---- Fast path: exact top-K over register-resident candidates ----
            unsigned v0 = (tid           < M) ? s_cand[tid]           : 0u;
            unsigned v1 = (tid + T       < M) ? s_cand[tid + T]       : 0u;
            unsigned v2 = (tid + 2 * T   < M) ? s_cand[tid + 2 * T]   : 0u;
            unsigned v3 = (tid + 3 * T   < M) ? s_cand[tid + 3 * T]   : 0u;

            // block max -> tight hi for search
            unsigned mx = v0 > v1 ? v0 : v1;
            unsigned m2 = v2 > v3 ? v2 : v3;
            mx = mx > m2 ? mx : m2;
            mx = warp_max_u(mx);
            if (lane == 0) s_wi[wid] = (int)mx;
            __syncthreads();
            if (tid < 32) {
                unsigned t = warp_max_u((unsigned)s_wi[lane]);
                if (lane == 0) { s_lo = __float_as_uint(P0F); s_hi = t + 1u; }
            }
            __syncthreads();

            // 3-way binary search on the exact uint threshold
            for (int s = 0; s < 64; s++) {
                const unsigned lo = s_lo, hi = s_hi;
                const unsigned w = hi - lo;
                if (w <= 1u) break;
                const unsigned d = w / 3u;
                const unsigned b1 = lo + (d > 1u ? d : 1u);
                unsigned t2 = 2u * d;
                if (t2 < 2u) t2 = 2u;
                if (t2 > w - 1u) t2 = w - 1u;
                const unsigned b2 = lo + t2;

                int c12 = 0;
                c12 += (v0 >= b1) + ((v0 >= b2) ? 0x10000 : 0);
                c12 += (v1 >= b1) + ((v1 >= b2) ? 0x10000 : 0);
                c12 += (v2 >= b1) + ((v2 >= b2) ? 0x10000 : 0);
                c12 += (v3 >= b1) + ((v3 >= b2) ? 0x10000 : 0);
                c12 = warp_sum_i(c12);
                if (lane == 0) s_wi[wid] = c12;
                __syncthreads();
                if (tid < 32) {
                    int t = warp_sum_i(s_wi[lane]);
                    if (lane == 0) {
                        const int C1 = t & 0xFFFF;
                        const int C2 = t >> 16;
                        if (C2 >= K)      s_lo = b2;
                        else if (C1 >= K) { s_lo = b1; s_hi = b2; }
                        else              s_hi = b1;
                    }
                }
                __syncthreads();
            }
            const unsigned lo = s_lo;

            // exact: sum strictly above threshold + tie copies at exact value
            float sa = 0.f;
            int ca = 0;
            if (v0 > lo) { sa += __uint_as_float(v0); ca++; }
            if (v1 > lo) { sa += __uint_as_float(v1); ca++; }
            if (v2 > lo) { sa += __uint_as_float(v2); ca++; }
            if (v3 > lo) { sa += __uint_as_float(v3); ca++; }
            sa = warp_sum(sa);
            ca = warp_sum_i(ca);
            if (lane == 0) { s_wf[wid] = sa; s_wi[wid] = ca; }
            __syncthreads();
            if (tid < 32) {
                float fs = warp_sum(s_wf[lane]);
                int   cs = warp_sum_i(s_wi[lane]);
                if (lane == 0) s_top = fs + (float)(K - cs) * __uint_as_float(lo);
            }
            __syncthreads();
        } else {
            // ---- Fallback (exact, slow; statistically never taken) ----
            int K_eff = NANCH - pos_num;          // number of negatives
            if (K < K_eff) K_eff = K;
            if (K_eff > 0) {
                if (tid == 0) { s_lo = 0u; s_hi = 0x7F800000u; }
                __syncthreads();
                for (int s = 0; s < 96; s++) {
                    const unsigned lo = s_lo, hi = s_hi;
                    const unsigned w = hi - lo;
                    if (w <= 1u) break;
                    const unsigned d = w / 3u;
                    const unsigned b1 = lo + (d > 1u ? d : 1u);
                    unsigned t2 = 2u * d;
                    if (t2 < 2u) t2 = 2u;
                    if (t2 > w - 1u) t2 = w - 1u;
                    const unsigned b2 = lo + t2;

                    int c12 = 0;
                    for (int it = 0; it < NIT; it++) {
                        const int i4 = tid + it * T;
                        if (i4 < NQ) {
                            float4 xv = pl4[i4];
                            float4 yv = gl4[i4];
                            #pragma unroll
                            for (int c = 0; c < 4; c++) {
                                float x = (c == 0) ? xv.x : (c == 1) ? xv.y : (c == 2) ? xv.z : xv.w;
                                float y = (c == 0) ? yv.x : (c == 1) ? yv.y : (c == 2) ? yv.z : yv.w;
                                if (!(y > 0.f)) {
                                    unsigned u = __float_as_uint(bce_of(x, y));
                                    c12 += (u >= b1) + ((u >= b2) ? 0x10000 : 0);
                                }
                            }
                        }
                    }
                    c12 = warp_sum_i(c12);
                    if (lane == 0) s_wi[wid] = c12;
                    __syncthreads();
                    if (tid < 32) {
                        int t = warp_sum_i(s_wi[lane]);
                        if (lane == 0) {
                            const int C1 = t & 0xFFFF;
                            const int C2 = t >> 16;
                            if (C2 >= K_eff)      s_lo = b2;
                            else if (C1 >= K_eff) { s_lo = b1; s_hi = b2; }
                            else                  s_hi = b1;
                        }
                    }
                    __syncthreads();
                }
                const unsigned lo = s_lo;
                float sa = 0.f;
                int ca = 0;
                for (int it = 0; it < NIT; it++) {
                    const int i4 = tid + it * T;
                    if (i4 < NQ) {
                        float4 xv = pl4[i4];
                        float4 yv = gl4[i4];
                        #pragma unroll
                        for (int c = 0; c < 4; c++) {
                            float x = (c == 0) ? xv.x : (c == 1) ? xv.y : (c == 2) ? xv.z : xv.w;
                            float y = (c == 0) ? yv.x : (c == 1) ? yv.y : (c == 2) ? yv.z : yv.w;
                            if (!(y > 0.f)) {
                                unsigned u = __float_as_uint(bce_of(x, y));
                                if (u > lo) { sa += __uint_as_float(u); ca++; }
                            }
                        }
                    }
                }
                sa = warp_sum(sa);
                ca = warp_sum_i(ca);
                if (lane == 0) { s_wf[wid] = sa; s_wi[wid] = ca; }
                __syncthreads();
                if (tid < 32) {
                    float fs = warp_sum(s_wf[lane]);
                    int   cs = warp_sum_i(s_wi[lane]);
                    if (lane == 0) s_top = fs + (float)(K_eff - cs) * __uint_as_float(lo);
                }
                __syncthreads();
            }
        }
    }
    const float sum_top = (K > 0) ? s_top : 0.f;

    // ---- Publish row; last block does the final reduction ----
    if (tid == 0) {
        g_row_posn[b]  = pos_num;
        g_row_lossb[b] = s_sl1;
        g_row_lossl[b] = s_bce + sum_top;
        __threadfence();
        int prev = atomicAdd(&g_done, 1);
        s_last = (prev == BATCH - 1);
    }
    __syncthreads();

    if (s_last) {
        float vlb = 0.f, vll = 0.f, vm = 0.f;
        if (tid < BATCH) {
            float pn  = (float)((volatile int*)g_row_posn)[tid];
            float lbv = ((volatile float*)g_row_lossb)[tid];
            float llv = ((volatile float*)g_row_lossl)[tid];
            float mask = (pn > 0.f) ? 1.f : 0.f;
            float wgt  = mask / fmaxf(pn, FLT_EPS_);
            vlb = lbv * wgt;
            vll = llv * wgt;
            vm  = wgt;
        }
        vlb = warp_sum(vlb);
        vll = warp_sum(vll);
        vm  = warp_sum(vm);
        if (lane == 0) {
            s_red[wid * 3 + 0] = vlb;
            s_red[wid * 3 + 1] = vll;
            s_red[wid * 3 + 2] = vm;
        }
        __syncthreads();
        if (tid == 0) {
            float slb = 0.f, sll = 0.f, sm = 0.f;
            #pragma unroll
            for (int w = 0; w < NW; w++) {
                slb += s_red[w * 3 + 0];
                sll += s_red[w * 3 + 1];
                sm  += s_red[w * 3 + 2];
            }
            const float lb = slb / (float)BATCH;
            const float ll = sll / (float)BATCH;
            const float total = (lb + ll) * (sm / (float)BATCH);
            if (out_size >= 1) out[0] = total;
            if (out_size >= 2) out[1] = lb;
            if (out_size >= 3) out[2] = ll;
            g_done = 0;  // reset for next graph replay
        }
    }
}

extern "C" void kernel_launch(void* const* d_in, const int* in_sizes, int n_in,
                              void* d_out, int out_size) {
    const float* pbboxs  = (const float*)d_in[0];
    const float* plabels = (const float*)d_in[1];
    const float* gbboxs  = (const float*)d_in[2];
    const float* glabels = (const float*)d_in[3];
    const float* ancs    = (const float*)d_in[4];
    (void)in_sizes; (void)n_in;

    od_fused<<<BATCH, T>>>(pbboxs, plabels, gbboxs, glabels, ancs,
                           (float*)d_out, out_size);
}